// round 3
// baseline (speedup 1.0000x reference)
#include <cuda_runtime.h>
#include <math.h>
#include <stdint.h>

// ---------------- problem constants ----------------
#define MTOT 36992            // 32 * 34 * 34 flattened padded rows
#define KTOT 2304             // 9 taps * 256 channels
#define CHUNKS 18             // 9 taps * 2 half-channel groups (128B of K each)
#define STAGES 3

// ---------------- device scratch (no allocs allowed) ----------------
__device__ __align__(256) int8_t g_xq[(size_t)32 * 34 * 34 * 256]; // [b][hp][wp][c], halo zero
__device__ __align__(256) int8_t g_wq[(size_t)256 * KTOT];         // [o][tap*256 + c] ternary
__device__ float g_scale[256];
__device__ float g_bias[256];

// ---------------------------------------------------------------------------
// Pre-pass A: quantize x to int8 (scale 2^-7), NCHW -> padded NHWC
// ---------------------------------------------------------------------------
__global__ void quantX_kernel(const float* __restrict__ x) {
    __shared__ int8_t s[256][33];
    int b = blockIdx.x, h = blockIdx.y;
    int w  = threadIdx.x & 31;
    int cg = threadIdx.x >> 5;
#pragma unroll
    for (int c0 = 0; c0 < 256; c0 += 8) {
        int c = c0 + cg;
        float v = x[(((size_t)(b * 256 + c) * 32 + h) * 32) + w];
        float r = rintf(v * 128.0f);
        r = fminf(fmaxf(r, -128.0f), 127.0f);
        s[c][w] = (int8_t)(int)r;
    }
    __syncthreads();
    size_t base = (((size_t)(b * 34 + h + 1)) * 34 + 1) * 256;
#pragma unroll
    for (int it = 0; it < 8; ++it) {
        int idx = it * 256 + threadIdx.x;
        int w2 = idx >> 6, cw = idx & 63;
        char4 v;
        v.x = s[cw * 4 + 0][w2];
        v.y = s[cw * 4 + 1][w2];
        v.z = s[cw * 4 + 2][w2];
        v.w = s[cw * 4 + 3][w2];
        *reinterpret_cast<char4*>(&g_xq[base + (size_t)w2 * 256 + cw * 4]) = v;
    }
}

// ---------------------------------------------------------------------------
// Pre-pass B: ternary weights, OIHW -> [o][tap*256 + c]
// ---------------------------------------------------------------------------
__global__ void quantW_kernel(const float* __restrict__ wt) {
    int idx = blockIdx.x * 256 + threadIdx.x;   // 589824 total
    int o = idx / KTOT;
    int r = idx - o * KTOT;
    int t = r >> 8;
    int c = r & 255;
    float v = wt[((size_t)(o * 256 + c)) * 9 + t];
    float q = rintf(v);
    q = fminf(fmaxf(q, -1.0f), 1.0f);
    g_wq[(size_t)o * KTOT + r] = (int8_t)(int)q;
}

// ---------------------------------------------------------------------------
// Pre-pass C: BN fold
// ---------------------------------------------------------------------------
__global__ void bn_kernel(const float* __restrict__ g, const float* __restrict__ be,
                          const float* __restrict__ m, const float* __restrict__ v) {
    int o = threadIdx.x;
    double invd = (double)g[o] / sqrt((double)v[o] + 1e-4);
    float invf = (float)invd;
    g_scale[o] = invf;
    g_bias[o]  = __fadd_rn(be[o], -__fmul_rn(m[o], invf));
}

// ---------------- helpers ----------------
__device__ __forceinline__ uint32_t smem_u32(const void* p) {
    uint32_t a;
    asm("{ .reg .u64 t; cvta.to.shared.u64 t, %1; cvt.u32.u64 %0, t; }" : "=r"(a) : "l"(p));
    return a;
}
__device__ __forceinline__ void cp_async_16(uint32_t dst, const void* src, unsigned srcsz) {
    asm volatile("cp.async.cg.shared.global [%0], [%1], 16, %2;"
                 :: "r"(dst), "l"(src), "r"(srcsz));
}
__device__ __forceinline__ void ldsm_x4(uint32_t* r, uint32_t addr) {
    asm volatile("ldmatrix.sync.aligned.m8n8.x4.shared.b16 {%0,%1,%2,%3}, [%4];"
                 : "=r"(r[0]), "=r"(r[1]), "=r"(r[2]), "=r"(r[3]) : "r"(addr));
}
__device__ __forceinline__ void imma(int* c, const uint32_t* a, uint32_t b0, uint32_t b1) {
    asm volatile(
        "mma.sync.aligned.m16n8k32.row.col.s32.s8.s8.s32 "
        "{%0,%1,%2,%3}, {%4,%5,%6,%7}, {%8,%9}, {%0,%1,%2,%3};"
        : "+r"(c[0]), "+r"(c[1]), "+r"(c[2]), "+r"(c[3])
        : "r"(a[0]), "r"(a[1]), "r"(a[2]), "r"(a[3]), "r"(b0), "r"(b1));
}

// stage layout: stage s at s*32768: A tile 128x128B (16KB), B tile 128x128B (16KB)
#define STAGE_SZ 32768
#define SMEM_BYTES (STAGES * STAGE_SZ)    // 98304

__global__ void __launch_bounds__(256, 2) conv_imma_kernel(float* __restrict__ out) {
    extern __shared__ char smem[];
    const uint32_t sb = smem_u32(smem);
    const int tid  = threadIdx.x;
    const int wid  = tid >> 5;
    const int lane = tid & 31;
    const int m0 = blockIdx.x * 128;
    const int n0 = blockIdx.y * 128;
    const int wm = wid & 1;        // 2 warps along M (64 each)
    const int wn = wid >> 1;       // 4 warps along N (32 each)

    int acc[4][4][4];
#pragma unroll
    for (int mt = 0; mt < 4; ++mt)
#pragma unroll
        for (int nt = 0; nt < 4; ++nt)
#pragma unroll
            for (int r = 0; r < 4; ++r) acc[mt][nt][r] = 0;

    // ---- chunk loader: tap = ks>>1, half-channel hc = ks&1 ----
    auto load_chunk = [&](int ks, int stage) {
        const int tap = ks >> 1, hc = ks & 1;
        const int toff = (tap / 3 - 1) * 34 + (tap % 3) - 1;
        const long rowbase = (long)m0 + toff;
        const uint32_t stA = sb + stage * STAGE_SZ;
        const uint32_t stB = stA + 16384;
#pragma unroll
        for (int it = 0; it < 4; ++it) {
            int idx = it * 256 + tid;          // 0..1023
            int r = idx >> 3, c16 = idx & 7;
            uint32_t soff = (uint32_t)(r * 128 + ((c16 ^ (r & 7)) << 4));
            long gA = rowbase + r;
            const int8_t* srcA = g_xq + gA * 256 + hc * 128 + c16 * 16;
            unsigned szA = (gA >= 0 && gA < MTOT) ? 16u : 0u;
            cp_async_16(stA + soff, srcA, szA);
            const int8_t* srcB = g_wq + (size_t)(n0 + r) * KTOT + tap * 256 + hc * 128 + c16 * 16;
            cp_async_16(stB + soff, srcB, 16u);
        }
        asm volatile("cp.async.commit_group;" ::: "memory");
    };

    // ldmatrix per-thread row bases
    const int arow_b = wm * 64 + (lane & 15);
    const int ahalf  = lane >> 4;
    const int brow_b = wn * 32 + (lane & 7) + ((lane >> 4) << 3);
    const int bhalf  = (lane >> 3) & 1;

    // ---- prologue ----
#pragma unroll
    for (int s = 0; s < STAGES - 1; ++s) load_chunk(s, s);

    // ---- mainloop ----
    for (int ks = 0; ks < CHUNKS; ++ks) {
        asm volatile("cp.async.wait_group 1;" ::: "memory");
        __syncthreads();

        int nk = ks + STAGES - 1;
        if (nk < CHUNKS) load_chunk(nk, nk % STAGES);
        else asm volatile("cp.async.commit_group;" ::: "memory");

        const uint32_t stA = sb + (ks % STAGES) * STAGE_SZ;
        const uint32_t stB = stA + 16384;
#pragma unroll
        for (int k32 = 0; k32 < 4; ++k32) {
            uint32_t a[4][4];
#pragma unroll
            for (int mt = 0; mt < 4; ++mt) {
                int row = arow_b + mt * 16;
                uint32_t addr = stA + row * 128 + (((k32 * 2 + ahalf) ^ (row & 7)) << 4);
                ldsm_x4(a[mt], addr);
            }
            uint32_t bfr[2][4];
#pragma unroll
            for (int tp = 0; tp < 2; ++tp) {
                int row = brow_b + tp * 16;
                uint32_t addr = stB + row * 128 + (((k32 * 2 + bhalf) ^ (row & 7)) << 4);
                ldsm_x4(bfr[tp], addr);
            }
#pragma unroll
            for (int mt = 0; mt < 4; ++mt)
#pragma unroll
                for (int nt = 0; nt < 4; ++nt) {
                    const uint32_t* bb = bfr[nt >> 1];
                    int off = (nt & 1) * 2;
                    imma(acc[mt][nt], a[mt], bb[off], bb[off + 1]);
                }
        }
    }

    // ---- epilogue: regs -> smem (transpose) -> quantize -> coalesced store ----
    __syncthreads();
    int* sEp = reinterpret_cast<int*>(smem);      // [128][129]
    const int gq = lane >> 2, tg = lane & 3;
#pragma unroll
    for (int mt = 0; mt < 4; ++mt) {
        int m = wm * 64 + mt * 16 + gq;
#pragma unroll
        for (int nt = 0; nt < 4; ++nt) {
            int n = wn * 32 + nt * 8 + tg * 2;
            sEp[m * 129 + n]           = acc[mt][nt][0];
            sEp[m * 129 + n + 1]       = acc[mt][nt][1];
            sEp[(m + 8) * 129 + n]     = acc[mt][nt][2];
            sEp[(m + 8) * 129 + n + 1] = acc[mt][nt][3];
        }
    }
    __syncthreads();

#pragma unroll 4
    for (int i = 0; i < 64; ++i) {
        int idx = i * 256 + tid;
        int m  = idx & 127;
        int oc = idx >> 7;
        int p = m0 + m;
        int b = p / 1156;
        int rem = p - b * 1156;
        int hp = rem / 34;
        int wp = rem - hp * 34;
        if (hp >= 1 && hp <= 32 && wp >= 1 && wp <= 32) {
            int o = n0 + oc;
            float y = __fmul_rn(__fmul_rn((float)sEp[m * 129 + oc], 0.0078125f), g_scale[o]);
            y = __fadd_rn(y, g_bias[o]);
            float r = rintf(__fmul_rn(y, 2.0f));
            r = fminf(fmaxf(r, -2.0f), 1.0f);
            out[(((size_t)b * 256 + o) * 32 + hp - 1) * 32 + wp - 1] = __fmul_rn(r, 0.5f);
        }
    }
}

extern "C" void kernel_launch(void* const* d_in, const int* in_sizes, int n_in,
                              void* d_out, int out_size) {
    const float* x     = (const float*)d_in[0];
    const float* wt    = (const float*)d_in[1];
    const float* gamma = (const float*)d_in[2];
    const float* beta  = (const float*)d_in[3];
    const float* mean  = (const float*)d_in[4];
    const float* var   = (const float*)d_in[5];
    float* out = (float*)d_out;

    void* xq_ptr = nullptr;
    cudaGetSymbolAddress(&xq_ptr, g_xq);
    cudaMemsetAsync(xq_ptr, 0, sizeof(g_xq), 0);

    quantX_kernel<<<dim3(32, 32), 256>>>(x);
    quantW_kernel<<<2304, 256>>>(wt);
    bn_kernel<<<1, 256>>>(gamma, beta, mean, var);

    cudaFuncSetAttribute(conv_imma_kernel, cudaFuncAttributeMaxDynamicSharedMemorySize, SMEM_BYTES);
    conv_imma_kernel<<<dim3(289, 2), 256, SMEM_BYTES>>>(out);
}

// round 4
// speedup vs baseline: 1.1796x; 1.1796x over previous
#include <cuda_runtime.h>
#include <math.h>
#include <stdint.h>

// ---------------- problem constants ----------------
#define MTOT 36992            // 32 * 34 * 34 flattened padded rows
#define KTOT 2304             // 9 taps * 256 channels
#define CHUNKS 18             // 9 taps * 2 half-channel groups (128B of K each)
#define STAGES 3

// ---------------- device scratch (no allocs allowed) ----------------
__device__ __align__(256) int8_t g_xq[(size_t)32 * 34 * 34 * 256]; // [b][hp][wp][c], halo zero
__device__ __align__(256) int8_t g_wq[(size_t)256 * KTOT];         // [o][tap*256 + c] ternary
__device__ float g_scale[256];
__device__ float g_bias[256];

// ---------------------------------------------------------------------------
// Pre-pass A: quantize x to int8 (scale 2^-7), NCHW -> padded NHWC
// ---------------------------------------------------------------------------
__global__ void quantX_kernel(const float* __restrict__ x) {
    __shared__ int8_t s[256][33];
    int b = blockIdx.x, h = blockIdx.y;
    int w  = threadIdx.x & 31;
    int cg = threadIdx.x >> 5;
#pragma unroll
    for (int c0 = 0; c0 < 256; c0 += 8) {
        int c = c0 + cg;
        float v = x[(((size_t)(b * 256 + c) * 32 + h) * 32) + w];
        float r = rintf(v * 128.0f);
        r = fminf(fmaxf(r, -128.0f), 127.0f);
        s[c][w] = (int8_t)(int)r;
    }
    __syncthreads();
    size_t base = (((size_t)(b * 34 + h + 1)) * 34 + 1) * 256;
#pragma unroll
    for (int it = 0; it < 8; ++it) {
        int idx = it * 256 + threadIdx.x;
        int w2 = idx >> 6, cw = idx & 63;
        char4 v;
        v.x = s[cw * 4 + 0][w2];
        v.y = s[cw * 4 + 1][w2];
        v.z = s[cw * 4 + 2][w2];
        v.w = s[cw * 4 + 3][w2];
        *reinterpret_cast<char4*>(&g_xq[base + (size_t)w2 * 256 + cw * 4]) = v;
    }
}

// ---------------------------------------------------------------------------
// Pre-pass B: ternary weights, OIHW -> [o][tap*256 + c]
// ---------------------------------------------------------------------------
__global__ void quantW_kernel(const float* __restrict__ wt) {
    int idx = blockIdx.x * 256 + threadIdx.x;   // 589824 total
    int o = idx / KTOT;
    int r = idx - o * KTOT;
    int t = r >> 8;
    int c = r & 255;
    float v = wt[((size_t)(o * 256 + c)) * 9 + t];
    float q = rintf(v);
    q = fminf(fmaxf(q, -1.0f), 1.0f);
    g_wq[(size_t)o * KTOT + r] = (int8_t)(int)q;
}

// ---------------------------------------------------------------------------
// Pre-pass C: BN fold
// ---------------------------------------------------------------------------
__global__ void bn_kernel(const float* __restrict__ g, const float* __restrict__ be,
                          const float* __restrict__ m, const float* __restrict__ v) {
    int o = threadIdx.x;
    double invd = (double)g[o] / sqrt((double)v[o] + 1e-4);
    float invf = (float)invd;
    g_scale[o] = invf;
    g_bias[o]  = __fadd_rn(be[o], -__fmul_rn(m[o], invf));
}

// ---------------- helpers ----------------
__device__ __forceinline__ uint32_t smem_u32(const void* p) {
    uint32_t a;
    asm("{ .reg .u64 t; cvta.to.shared.u64 t, %1; cvt.u32.u64 %0, t; }" : "=r"(a) : "l"(p));
    return a;
}
__device__ __forceinline__ void cp_async_16(uint32_t dst, const void* src, unsigned srcsz) {
    asm volatile("cp.async.cg.shared.global [%0], [%1], 16, %2;"
                 :: "r"(dst), "l"(src), "r"(srcsz));
}
__device__ __forceinline__ void ldsm_x4(uint32_t* r, uint32_t addr) {
    asm volatile("ldmatrix.sync.aligned.m8n8.x4.shared.b16 {%0,%1,%2,%3}, [%4];"
                 : "=r"(r[0]), "=r"(r[1]), "=r"(r[2]), "=r"(r[3]) : "r"(addr));
}
__device__ __forceinline__ void imma(int* c, const uint32_t* a, uint32_t b0, uint32_t b1) {
    asm volatile(
        "mma.sync.aligned.m16n8k32.row.col.s32.s8.s8.s32 "
        "{%0,%1,%2,%3}, {%4,%5,%6,%7}, {%8,%9}, {%0,%1,%2,%3};"
        : "+r"(c[0]), "+r"(c[1]), "+r"(c[2]), "+r"(c[3])
        : "r"(a[0]), "r"(a[1]), "r"(a[2]), "r"(a[3]), "r"(b0), "r"(b1));
}

// stage: A tile 128 rows x 128B (16KB) + B tile 256 rows x 128B (32KB)
#define STAGE_SZ 49152
#define SMEM_BYTES (STAGES * STAGE_SZ)    // 147456
#define EPS 257                            // epilogue smem row stride (ints)

__global__ void __launch_bounds__(512, 1) conv_hybrid_kernel(float* __restrict__ out) {
    extern __shared__ char smem[];
    const uint32_t sb = smem_u32(smem);
    const int tid  = threadIdx.x;
    const int wid  = tid >> 5;
    const int lane = tid & 31;
    const int m0 = blockIdx.x * 128;

    // tensor accs (warps 0-7): warp tile 64M x 32N
    int acc[4][4][4];
    // dp4a accs (warps 8-15): 4m x 16o per thread
    int accd[4][16];
    if (wid < 8) {
#pragma unroll
        for (int mt = 0; mt < 4; ++mt)
#pragma unroll
            for (int nt = 0; nt < 4; ++nt)
#pragma unroll
                for (int r = 0; r < 4; ++r) acc[mt][nt][r] = 0;
    } else {
#pragma unroll
        for (int i = 0; i < 4; ++i)
#pragma unroll
            for (int o = 0; o < 16; ++o) accd[i][o] = 0;
    }

    // ---- chunk loader: tap = ks>>1, half-channel hc = ks&1; all 512 threads ----
    auto load_chunk = [&](int ks, int stage) {
        const int tap = ks >> 1, hc = ks & 1;
        const int toff = (tap / 3 - 1) * 34 + (tap % 3) - 1;
        const long rowbase = (long)m0 + toff;
        const uint32_t stA = sb + stage * STAGE_SZ;
        const uint32_t stB = stA + 16384;
#pragma unroll
        for (int it = 0; it < 6; ++it) {
            int idx = it * 512 + tid;          // 0..3071
            if (idx < 1024) {                  // A: 128 rows x 8 chunks
                int r = idx >> 3, c16 = idx & 7;
                uint32_t soff = (uint32_t)(r * 128 + ((c16 ^ (r & 7)) << 4));
                long gA = rowbase + r;
                const int8_t* srcA = g_xq + gA * 256 + hc * 128 + c16 * 16;
                unsigned szA = (gA >= 0 && gA < MTOT) ? 16u : 0u;
                cp_async_16(stA + soff, srcA, szA);
            } else {                           // B: 256 rows x 8 chunks
                int j = idx - 1024;
                int r = j >> 3, c16 = j & 7;
                uint32_t soff = (uint32_t)(r * 128 + ((c16 ^ (r & 7)) << 4));
                const int8_t* srcB = g_wq + (size_t)r * KTOT + tap * 256 + hc * 128 + c16 * 16;
                cp_async_16(stB + soff, srcB, 16u);
            }
        }
        asm volatile("cp.async.commit_group;" ::: "memory");
    };

    // tensor ldmatrix per-thread row bases (N block = 0..127)
    const int wm = wid & 1, wn = wid >> 1;
    const int arow_b = wm * 64 + (lane & 15);
    const int ahalf  = lane >> 4;
    const int brow_b = wn * 32 + (lane & 7) + ((lane >> 4) << 3);
    const int bhalf  = (lane >> 3) & 1;
    // dp4a ids
    const int wd = wid - 8;

    // ---- prologue ----
#pragma unroll
    for (int s = 0; s < STAGES - 1; ++s) load_chunk(s, s);

    // ---- mainloop ----
    for (int ks = 0; ks < CHUNKS; ++ks) {
        asm volatile("cp.async.wait_group 1;" ::: "memory");
        __syncthreads();

        int nk = ks + STAGES - 1;
        if (nk < CHUNKS) load_chunk(nk, nk % STAGES);
        else asm volatile("cp.async.commit_group;" ::: "memory");

        const int st = ks % STAGES;
        if (wid < 8) {
            // ---------------- tensor half: N[0:128] ----------------
            const uint32_t stA = sb + st * STAGE_SZ;
            const uint32_t stB = stA + 16384;
#pragma unroll
            for (int k32 = 0; k32 < 4; ++k32) {
                uint32_t a[4][4];
#pragma unroll
                for (int mt = 0; mt < 4; ++mt) {
                    int row = arow_b + mt * 16;
                    uint32_t addr = stA + row * 128 + (((k32 * 2 + ahalf) ^ (row & 7)) << 4);
                    ldsm_x4(a[mt], addr);
                }
                uint32_t bfr[2][4];
#pragma unroll
                for (int tp = 0; tp < 2; ++tp) {
                    int row = brow_b + tp * 16;
                    uint32_t addr = stB + row * 128 + (((k32 * 2 + bhalf) ^ (row & 7)) << 4);
                    ldsm_x4(bfr[tp], addr);
                }
#pragma unroll
                for (int mt = 0; mt < 4; ++mt)
#pragma unroll
                    for (int nt = 0; nt < 4; ++nt) {
                        const uint32_t* bb = bfr[nt >> 1];
                        int off = (nt & 1) * 2;
                        imma(acc[mt][nt], a[mt], bb[off], bb[off + 1]);
                    }
            }
        } else {
            // ---------------- dp4a half: N[128:256] ----------------
            const char* pA = smem + st * STAGE_SZ;
            const char* pB = pA + 16384;
#pragma unroll
            for (int t = 0; t < 8; ++t) {
                int4 xv[4];
#pragma unroll
                for (int i = 0; i < 4; ++i) {
                    int r = lane + 32 * i;
                    xv[i] = *reinterpret_cast<const int4*>(pA + r * 128 + ((t ^ (r & 7)) << 4));
                }
#pragma unroll
                for (int ob = 0; ob < 4; ++ob) {
                    int4 wv[4];
#pragma unroll
                    for (int oo = 0; oo < 4; ++oo) {
                        int rB = 128 + wd * 16 + ob * 4 + oo;
                        wv[oo] = *reinterpret_cast<const int4*>(pB + rB * 128 + ((t ^ (rB & 7)) << 4));
                    }
#pragma unroll
                    for (int oo = 0; oo < 4; ++oo) {
                        int o = ob * 4 + oo;
#pragma unroll
                        for (int i = 0; i < 4; ++i) {
                            accd[i][o] = __dp4a(xv[i].x, wv[oo].x, accd[i][o]);
                            accd[i][o] = __dp4a(xv[i].y, wv[oo].y, accd[i][o]);
                            accd[i][o] = __dp4a(xv[i].z, wv[oo].z, accd[i][o]);
                            accd[i][o] = __dp4a(xv[i].w, wv[oo].w, accd[i][o]);
                        }
                    }
                }
            }
        }
    }

    // ---- epilogue: all results -> smem -> quantize -> coalesced store ----
    asm volatile("cp.async.wait_group 0;" ::: "memory");
    __syncthreads();
    int* sEp = reinterpret_cast<int*>(smem);      // [128][EPS]
    if (wid < 8) {
        const int gq = lane >> 2, tg = lane & 3;
#pragma unroll
        for (int mt = 0; mt < 4; ++mt) {
            int m = wm * 64 + mt * 16 + gq;
#pragma unroll
            for (int nt = 0; nt < 4; ++nt) {
                int n = wn * 32 + nt * 8 + tg * 2;
                sEp[m * EPS + n]           = acc[mt][nt][0];
                sEp[m * EPS + n + 1]       = acc[mt][nt][1];
                sEp[(m + 8) * EPS + n]     = acc[mt][nt][2];
                sEp[(m + 8) * EPS + n + 1] = acc[mt][nt][3];
            }
        }
    } else {
#pragma unroll
        for (int i = 0; i < 4; ++i) {
            int m = lane + 32 * i;
#pragma unroll
            for (int o = 0; o < 16; ++o)
                sEp[m * EPS + 128 + wd * 16 + o] = accd[i][o];
        }
    }
    __syncthreads();

#pragma unroll 4
    for (int i = 0; i < 64; ++i) {
        int idx = i * 512 + tid;
        int m  = idx & 127;
        int oc = idx >> 7;
        int p = m0 + m;
        int b = p / 1156;
        int rem = p - b * 1156;
        int hp = rem / 34;
        int wp = rem - hp * 34;
        if (b < 32 && hp >= 1 && hp <= 32 && wp >= 1 && wp <= 32) {
            float y = __fmul_rn(__fmul_rn((float)sEp[m * EPS + oc], 0.0078125f), g_scale[oc]);
            y = __fadd_rn(y, g_bias[oc]);
            float r = rintf(__fmul_rn(y, 2.0f));
            r = fminf(fmaxf(r, -2.0f), 1.0f);
            out[(((size_t)b * 256 + oc) * 32 + hp - 1) * 32 + wp - 1] = __fmul_rn(r, 0.5f);
        }
    }
}

extern "C" void kernel_launch(void* const* d_in, const int* in_sizes, int n_in,
                              void* d_out, int out_size) {
    const float* x     = (const float*)d_in[0];
    const float* wt    = (const float*)d_in[1];
    const float* gamma = (const float*)d_in[2];
    const float* beta  = (const float*)d_in[3];
    const float* mean  = (const float*)d_in[4];
    const float* var   = (const float*)d_in[5];
    float* out = (float*)d_out;

    void* xq_ptr = nullptr;
    cudaGetSymbolAddress(&xq_ptr, g_xq);
    cudaMemsetAsync(xq_ptr, 0, sizeof(g_xq), 0);

    quantX_kernel<<<dim3(32, 32), 256>>>(x);
    quantW_kernel<<<2304, 256>>>(wt);
    bn_kernel<<<1, 256>>>(gamma, beta, mean, var);

    cudaFuncSetAttribute(conv_hybrid_kernel, cudaFuncAttributeMaxDynamicSharedMemorySize, SMEM_BYTES);
    conv_hybrid_kernel<<<289, 512, SMEM_BYTES>>>(out);
}